// round 1
// baseline (speedup 1.0000x reference)
#include <cuda_runtime.h>

// AdvectionDiffusionReaction2M: N=512 grid, 199 explicit FD steps, all states output.
// Step t reads slab t-1 of d_out (u0 for t=0), writes slab t. No scratch memory.
//
// Closed-form per-cell update derived from the reference's assignment order:
//   ic = clamp(i,1,N-2), jc = clamp(j,1,N-2)
//   out(i,j) = (jc == ii) ? interface(ic) : interior(ic,jc)
// where ii = MB-1 = 255,
//   interface(i) = (k1*T[i,ii+1] + k2*T[i,ii-1]) / (k1+k2)
//   interior(i,j): radius-1 stencil with column-dependent (kappa, alpha).

#define NN      512
#define MBV     256
#define IIV     255
#define NSTEPS  199   // NUM_STEPS - 1

static __device__ __forceinline__ float clampf_idx(int v, int lo, int hi) {
    return (float)0; // unused
}

__global__ void adr_step_kernel(const float* __restrict__ Tin,
                                float*       __restrict__ Tout,
                                const float* __restrict__ k1p,
                                const float* __restrict__ k2p,
                                const float* __restrict__ a1p,
                                const float* __restrict__ a2p)
{
    const int j = blockIdx.x * blockDim.x + threadIdx.x;
    const int i = blockIdx.y;
    if (j >= NN) return;

    // Scalars (1-element device arrays) — broadcast loads, L2/const-cache hits.
    const float k1 = __ldg(k1p);
    const float k2 = __ldg(k2p);
    const float a1 = __ldg(a1p);
    const float a2 = __ldg(a2p);

    // Match the reference's float32 constants (python f64 -> f32 weak-type).
    const double DXd   = 1.0 / 511.0;
    const float  dx2   = (float)(DXd * DXd);
    const float  twodx = (float)(2.0 * DXd);
    const float  DT    = 1e-7f;

    const int ic = min(max(i, 1), NN - 2);
    const int jc = min(max(j, 1), NN - 2);

    float out;
    if (jc == IIV) {
        // Interface column: uses OLD field values, column-uniform k_left=k1, k_right=k2.
        const float Tr = Tin[ic * NN + (IIV + 1)];
        const float Tl = Tin[ic * NN + (IIV - 1)];
        out = (k1 * Tr + k2 * Tl) / (k1 + k2);
    } else {
        const float Tc  = Tin[ic * NN + jc];
        const float Tup = Tin[(ic - 1) * NN + jc];
        const float Tdn = Tin[(ic + 1) * NN + jc];
        const float Tl  = Tin[ic * NN + (jc - 1)];
        const float Tr  = Tin[ic * NN + (jc + 1)];

        const float T_xx = (Tup - 2.0f * Tc + Tdn) / dx2;   // axis-0 (rows)
        const float T_yy = (Tl  - 2.0f * Tc + Tr ) / dx2;   // axis-1 (cols)
        const float T_x  = (Tdn - Tup) / twodx;
        const float T_y  = (Tr  - Tl ) / twodx;

        const float kap = (jc < MBV) ? k1 : k2;
        const float al  = (jc < MBV) ? a1 : a2;

        const float Tc2 = Tc * Tc;
        out = Tc
            - DT * (Tc2 * T_x - Tc * T_y) * kap
            + DT * al * (T_xx + T_yy)
            + DT * kap * (Tc2 * Tc - Tc2 + Tc);
    }

    Tout[i * NN + j] = out;
}

extern "C" void kernel_launch(void* const* d_in, const int* in_sizes, int n_in,
                              void* d_out, int out_size)
{
    const float* u0  = (const float*)d_in[0];
    const float* k1p = (const float*)d_in[1];
    const float* k2p = (const float*)d_in[2];
    const float* a1p = (const float*)d_in[3];
    const float* a2p = (const float*)d_in[4];
    float* out = (float*)d_out;

    dim3 block(128, 1, 1);
    dim3 grid(NN / 128, NN, 1);

    const float* src = u0;
    for (int t = 0; t < NSTEPS; ++t) {
        float* dst = out + (size_t)t * NN * NN;
        adr_step_kernel<<<grid, block>>>(src, dst, k1p, k2p, a1p, a2p);
        src = dst;
    }
}

// round 2
// speedup vs baseline: 1.5088x; 1.5088x over previous
#include <cuda_runtime.h>

// AdvectionDiffusionReaction2M — temporal-blocked stencil.
// 199 steps computed in chunks of S=8 steps per kernel launch (25 launches).
// Each block owns a TILE x TILE output tile; loads an EXT x EXT halo region
// into shared memory and advances S steps locally (overlapping-halo pyramid),
// writing its owned tile into every intermediate output slab.
//
// Per-cell closed form (validated round 1, rel_err 5.8e-8):
//   ic = clamp(i,1,510), jc = clamp(j,1,510)
//   out(i,j) = (jc == 255) ? (k1*T[ic,256] + k2*T[ic,254]) / (k1+k2)
//                          : radius-1 stencil at (ic,jc) with column-dep (kappa,alpha)

#define NN    512
#define N2    (NN * NN)
#define MBV   256
#define IIV   255
#define S     8               // steps per chunk (= halo width)
#define TILE  32              // owned tile edge
#define EXT   (TILE + 2 * S)  // 48: extended (halo) tile edge
#define NSTEPS 199

__global__ __launch_bounds__(256)
void adr_chunk_kernel(const float* __restrict__ src,   // field at step t0-1 (u0 for t0==0)
                      float*       __restrict__ out,   // all slabs
                      int t0, int nsteps,
                      const float* __restrict__ k1p,
                      const float* __restrict__ k2p,
                      const float* __restrict__ a1p,
                      const float* __restrict__ a2p)
{
    __shared__ float buf[2][EXT][EXT];   // row stride 48 floats -> conflict-free for 2-row warps

    const int tx = threadIdx.x;          // 0..15
    const int ty = threadIdx.y;          // 0..15

    const int ro0 = blockIdx.y * TILE;
    const int co0 = blockIdx.x * TILE;
    const int rbase = max(ro0 - S, 0);
    const int cbase = max(co0 - S, 0);
    const int re = min(ro0 + TILE + S, NN) - rbase;   // <= 48
    const int ce = min(co0 + TILE + S, NN) - cbase;   // <= 48

    const float k1 = __ldg(k1p);
    const float k2 = __ldg(k2p);
    const float a1 = __ldg(a1p);
    const float a2 = __ldg(a2p);
    const float inv_ksum = 1.0f / (k1 + k2);

    // f32 constants matching the reference's weak-typed scalars
    const float dx2f   = (float)((1.0 / 511.0) * (1.0 / 511.0));
    const float twodxf = (float)(2.0 / 511.0);
    const float inv_dx2   = 1.0f / dx2f;
    const float inv_twodx = 1.0f / twodxf;
    const float DT = 1e-7f;

    // ---- load extended region (step t0-1 field) ----
    #pragma unroll
    for (int ky = 0; ky < 3; ++ky)
        #pragma unroll
        for (int kx = 0; kx < 3; ++kx) {
            const int i = ty + 16 * ky;
            const int j = tx + 16 * kx;
            if (i < re && j < ce)
                buf[0][i][j] = src[(rbase + i) * NN + (cbase + j)];
        }
    __syncthreads();

    int p = 0;
    for (int k = 1; k <= nsteps; ++k) {
        const int h = S - k;  // remaining halo after this level (>= 0 since nsteps <= S)
        const int vr0 = max(ro0 - h, 0),        vr1 = min(ro0 + TILE + h, NN);
        const int vc0 = max(co0 - h, 0),        vc1 = min(co0 + TILE + h, NN);
        float* __restrict__ slab = out + (size_t)(t0 + k - 1) * N2;

        #pragma unroll
        for (int ky = 0; ky < 3; ++ky)
            #pragma unroll
            for (int kx = 0; kx < 3; ++kx) {
                const int i  = ty + 16 * ky;
                const int j  = tx + 16 * kx;
                const int gi = rbase + i;
                const int gj = cbase + j;
                if (gi >= vr0 && gi < vr1 && gj >= vc0 && gj < vc1) {
                    const int ic = min(max(gi, 1), NN - 2);
                    const int jc = min(max(gj, 1), NN - 2);
                    const int li = ic - rbase;
                    const int lj = jc - cbase;

                    float val;
                    if (jc == IIV) {
                        const float Tr = buf[p][li][lj + 1];
                        const float Tl = buf[p][li][lj - 1];
                        val = (k1 * Tr + k2 * Tl) * inv_ksum;
                    } else {
                        const float Tc  = buf[p][li][lj];
                        const float Tup = buf[p][li - 1][lj];
                        const float Tdn = buf[p][li + 1][lj];
                        const float Tl  = buf[p][li][lj - 1];
                        const float Tr  = buf[p][li][lj + 1];

                        const float T_xx = (Tup - 2.0f * Tc + Tdn) * inv_dx2;
                        const float T_yy = (Tl  - 2.0f * Tc + Tr ) * inv_dx2;
                        const float T_x  = (Tdn - Tup) * inv_twodx;
                        const float T_y  = (Tr  - Tl ) * inv_twodx;

                        const float kap = (jc < MBV) ? k1 : k2;
                        const float al  = (jc < MBV) ? a1 : a2;

                        const float Tc2 = Tc * Tc;
                        val = Tc
                            - DT * (Tc2 * T_x - Tc * T_y) * kap
                            + DT * al * (T_xx + T_yy)
                            + DT * kap * (Tc2 * Tc - Tc2 + Tc);
                    }

                    buf[p ^ 1][i][j] = val;

                    if (gi >= ro0 && gi < ro0 + TILE && gj >= co0 && gj < co0 + TILE)
                        slab[gi * NN + gj] = val;
                }
            }
        __syncthreads();
        p ^= 1;
    }
}

extern "C" void kernel_launch(void* const* d_in, const int* in_sizes, int n_in,
                              void* d_out, int out_size)
{
    const float* u0  = (const float*)d_in[0];
    const float* k1p = (const float*)d_in[1];
    const float* k2p = (const float*)d_in[2];
    const float* a1p = (const float*)d_in[3];
    const float* a2p = (const float*)d_in[4];
    float* out = (float*)d_out;

    dim3 block(16, 16, 1);
    dim3 grid(NN / TILE, NN / TILE, 1);   // 16 x 16 = 256 blocks

    int t0 = 0;
    while (t0 < NSTEPS) {
        const int nsteps = min(S, NSTEPS - t0);
        const float* src = (t0 == 0) ? u0 : (out + (size_t)(t0 - 1) * N2);
        adr_chunk_kernel<<<grid, block>>>(src, out, t0, nsteps, k1p, k2p, a1p, a2p);
        t0 += nsteps;
    }
}

// round 3
// speedup vs baseline: 2.2103x; 1.4650x over previous
#include <cuda_runtime.h>

// AdvectionDiffusionReaction2M — temporal-blocked stencil, register/shuffle version.
// 199 steps in chunks of S=8 per launch (25 launches). Grid 32x32 blocks, block (32,8).
// Each block owns a 16x16 tile, computes on a 32x32 extended region held in
// registers: thread (tx,ty) owns column gj = co0-8+tx, rows gi = ro0-8+4ty+{0..3}.
// Horizontal neighbors via warp shuffle, vertical strip boundaries via smem.
// Extended-rim garbage propagates inward 1 cell/level; owned core has exactly
// S=8 margin, so it is never contaminated.
//
// Validated closed form (rounds 1-2, rel_err 0):
//   interior stencil with column-dependent (kappa,alpha); col 255 = interface;
//   boundary rows/cols duplicate their inner neighbors (maintained as fixups).

#define NN     512
#define N2     (NN * NN)
#define S      8
#define TILE   16
#define EXT    32
#define NSTEPS 199

__device__ __forceinline__ float cellstep(float up, float dn, float c, float l, float r,
                                          float c_al, float cx, float ck)
{
    // laplacian term: DT*alpha*(T_xx+T_yy) = c_al * (up+dn+l+r - 4c)
    float s   = (up + dn) + (l + r);
    float lap = fmaf(-4.0f, c, s);
    // advection: -DT*kap*(c^2*T_x - c*T_y) = -cx * c*(c*(dn-up) + (l-r))
    float A   = fmaf(c, dn - up, l - r);
    float adv = c * A;
    // reaction: DT*kap*(c^3 - c^2 + c) = ck * c*(c^2 - c + 1)
    float q    = fmaf(c, c, -c);
    float reac = c * (q + 1.0f);

    float v = fmaf(c_al, lap, c);
    v = fmaf(-cx, adv, v);
    v = fmaf(ck, reac, v);
    return v;
}

__global__ __launch_bounds__(256)
void adr_chunk_kernel(const float* __restrict__ src,   // field at step t0-1
                      float*       __restrict__ out,
                      int t0, int nsteps,
                      const float* __restrict__ k1p,
                      const float* __restrict__ k2p,
                      const float* __restrict__ a1p,
                      const float* __restrict__ a2p)
{
    // strip-boundary exchange: thread's top row (r0) and bottom row (r3),
    // double-buffered, padded rows 0 and 9.
    __shared__ float s_top[2][10][EXT];
    __shared__ float s_bot[2][10][EXT];

    const int tx = threadIdx.x;   // 0..31 (column within extended tile)
    const int ty = threadIdx.y;   // 0..7  (4-row strip index; warp == row band)

    if (ty == 0) {
        s_top[0][0][tx] = 0.f; s_top[0][9][tx] = 0.f;
        s_top[1][0][tx] = 0.f; s_top[1][9][tx] = 0.f;
        s_bot[0][0][tx] = 0.f; s_bot[0][9][tx] = 0.f;
        s_bot[1][0][tx] = 0.f; s_bot[1][9][tx] = 0.f;
    }

    const int ro0 = blockIdx.y * TILE;
    const int co0 = blockIdx.x * TILE;
    const int rb  = ro0 - S;              // may be negative (ghost region)
    const int cb  = co0 - S;

    const int gj  = cb + tx;              // this thread's global column (may be out of range)
    const int gjc = min(max(gj, 0), NN - 1);

    const float k1 = __ldg(k1p), k2 = __ldg(k2p);
    const float a1 = __ldg(a1p), a2 = __ldg(a2p);
    const float inv_ksum = 1.0f / (k1 + k2);

    const float dx2f   = (float)((1.0 / 511.0) * (1.0 / 511.0));
    const float twodxf = (float)(2.0 / 511.0);
    const float DT     = 1e-7f;

    const float kap  = (gj < 256) ? k1 : k2;
    const float al   = (gj < 256) ? a1 : a2;
    const float c_al = DT * al / dx2f;
    const float cx   = DT * kap / twodxf;
    const float ck   = DT * kap;

    const bool iface_blk = (blockIdx.x == 15) || (blockIdx.x == 16);
    const bool is_if     = (gj == 255);
    const bool own_col   = (tx >= S) && (tx < S + TILE);
    const bool own_row   = (ty >= 2) && (ty < 6);

    // ---- initial load: 4 rows of this thread's strip (clamped) ----
    float r0, r1, r2, r3;
    {
        const int gi0 = rb + 4 * ty;
        r0 = src[min(max(gi0 + 0, 0), NN - 1) * NN + gjc];
        r1 = src[min(max(gi0 + 1, 0), NN - 1) * NN + gjc];
        r2 = src[min(max(gi0 + 2, 0), NN - 1) * NN + gjc];
        r3 = src[min(max(gi0 + 3, 0), NN - 1) * NN + gjc];
    }

    float* __restrict__ slab = out + (size_t)t0 * N2;
    const int sidx = (rb + 4 * ty) * NN + gj;   // only used when owned (in range)

    const unsigned FULL = 0xffffffffu;
    int pb = 0;

    for (int k = 0; k < nsteps; ++k) {
        s_top[pb][ty + 1][tx] = r0;
        s_bot[pb][ty + 1][tx] = r3;
        __syncthreads();
        const float up = s_bot[pb][ty][tx];       // row above this strip
        const float dn = s_top[pb][ty + 2][tx];   // row below this strip

        // horizontal neighbors (lane 0/31 wrap to self -> rim garbage, by design)
        float l0 = __shfl_up_sync(FULL, r0, 1), q0 = __shfl_down_sync(FULL, r0, 1);
        float l1 = __shfl_up_sync(FULL, r1, 1), q1 = __shfl_down_sync(FULL, r1, 1);
        float l2 = __shfl_up_sync(FULL, r2, 1), q2 = __shfl_down_sync(FULL, r2, 1);
        float l3 = __shfl_up_sync(FULL, r3, 1), q3 = __shfl_down_sync(FULL, r3, 1);

        float n0 = cellstep(up, r1, r0, l0, q0, c_al, cx, ck);
        float n1 = cellstep(r0, r2, r1, l1, q1, c_al, cx, ck);
        float n2 = cellstep(r1, r3, r2, l2, q2, c_al, cx, ck);
        float n3 = cellstep(r2, dn, r3, l3, q3, c_al, cx, ck);

        // interface column j=255: value from OLD neighbors (only blocks bx 15/16)
        if (iface_blk) {
            if (is_if) {
                n0 = (k1 * q0 + k2 * l0) * inv_ksum;
                n1 = (k1 * q1 + k2 * l1) * inv_ksum;
                n2 = (k1 * q2 + k2 * l2) * inv_ksum;
                n3 = (k1 * q3 + k2 * l3) * inv_ksum;
            }
        }

        // domain-boundary fixups: edge row/col duplicates inner neighbor.
        if (ro0 == 0 && ty == 2)         n0 = n1;   // gi=0  <- gi=1
        if (ro0 == NN - TILE && ty == 5) n3 = n2;   // gi=511 <- gi=510
        if (co0 == 0) {                              // gj=0 (tx=8) <- gj=1 (tx=9)
            float c0 = __shfl_down_sync(FULL, n0, 1);
            float c1 = __shfl_down_sync(FULL, n1, 1);
            float c2 = __shfl_down_sync(FULL, n2, 1);
            float c3 = __shfl_down_sync(FULL, n3, 1);
            if (tx == S) { n0 = c0; n1 = c1; n2 = c2; n3 = c3; }
        }
        if (co0 == NN - TILE) {                      // gj=511 (tx=23) <- gj=510 (tx=22)
            float c0 = __shfl_up_sync(FULL, n0, 1);
            float c1 = __shfl_up_sync(FULL, n1, 1);
            float c2 = __shfl_up_sync(FULL, n2, 1);
            float c3 = __shfl_up_sync(FULL, n3, 1);
            if (tx == S + TILE - 1) { n0 = c0; n1 = c1; n2 = c2; n3 = c3; }
        }

        // store owned 16x16 tile into this level's output slab
        if (own_row && own_col) {
            slab[sidx]          = n0;
            slab[sidx + NN]     = n1;
            slab[sidx + 2 * NN] = n2;
            slab[sidx + 3 * NN] = n3;
        }

        slab += N2;
        r0 = n0; r1 = n1; r2 = n2; r3 = n3;
        pb ^= 1;
    }
}

extern "C" void kernel_launch(void* const* d_in, const int* in_sizes, int n_in,
                              void* d_out, int out_size)
{
    const float* u0  = (const float*)d_in[0];
    const float* k1p = (const float*)d_in[1];
    const float* k2p = (const float*)d_in[2];
    const float* a1p = (const float*)d_in[3];
    const float* a2p = (const float*)d_in[4];
    float* out = (float*)d_out;

    dim3 block(32, 8, 1);
    dim3 grid(NN / TILE, NN / TILE, 1);   // 32 x 32 = 1024 blocks

    int t0 = 0;
    while (t0 < NSTEPS) {
        const int nsteps = min(S, NSTEPS - t0);
        const float* src = (t0 == 0) ? u0 : (out + (size_t)(t0 - 1) * N2);
        adr_chunk_kernel<<<grid, block>>>(src, out, t0, nsteps, k1p, k2p, a1p, a2p);
        t0 += nsteps;
    }
}

// round 4
// speedup vs baseline: 4.0601x; 1.8369x over previous
#include <cuda_runtime.h>

// AdvectionDiffusionReaction2M — temporal-blocked stencil, 4x4-cells-per-thread.
// 199 steps in chunks of S=8 per launch (25 launches). Grid 11x11 blocks,
// block (16,16). Each thread holds a 4x4 register sub-tile of a 64x64 extended
// tile; the block owns the central 48x48. Horizontal neighbors are in-register
// except strip edges (2 shfl/row); vertical strip boundaries exchanged via
// 128-bit smem ops. Rim garbage propagates 1 cell/level; owned core has
// exactly S=8 margin. Domain-edge fixups and the interface column j=255 are
// intra-thread (validated closed form, rounds 1-3).

#define NN     512
#define N2     (NN * NN)
#define S      8
#define TILEW  48
#define EXT    64
#define NSTEPS 199

__global__ __launch_bounds__(256)
void adr_chunk_kernel(const float* __restrict__ src,
                      float*       __restrict__ out,
                      int t0, int nsteps,
                      const float* __restrict__ k1p,
                      const float* __restrict__ k2p,
                      const float* __restrict__ a1p,
                      const float* __restrict__ a2p)
{
    // double-buffered strip-boundary rows; row index ty+1, pads at 0 and 17
    __shared__ float s_top[2][18][EXT];
    __shared__ float s_bot[2][18][EXT];

    const int tx = threadIdx.x;   // 0..15, owns cols 4tx..4tx+3 of ext tile
    const int ty = threadIdx.y;   // 0..15, owns rows 4ty..4ty+3

    const int ro0 = blockIdx.y * TILEW;
    const int co0 = blockIdx.x * TILEW;
    const int rb  = ro0 - S;
    const int cb  = co0 - S;
    const int gi0 = rb + 4 * ty;   // first global row of this thread (may be OOB)
    const int gj0 = cb + 4 * tx;   // first global col

    const float k1 = __ldg(k1p), k2 = __ldg(k2p);
    const float a1 = __ldg(a1p), a2 = __ldg(a2p);
    const float inv_ksum = 1.0f / (k1 + k2);

    const float dx2f   = (float)((1.0 / 511.0) * (1.0 / 511.0));
    const float twodxf = (float)(2.0 / 511.0);
    const float DT     = 1e-7f;

    // 4-col packs never straddle j=256 (256 - cb is a multiple of 4)
    const float kap  = (gj0 < 256) ? k1 : k2;
    const float al   = (gj0 < 256) ? a1 : a2;
    const float c_al = DT * al / dx2f;
    const float cx   = DT * kap / twodxf;
    const float ck   = DT * kap;

    // ---- clamped initial load (field at step t0-1) ----
    float v[4][4];
    #pragma unroll
    for (int r = 0; r < 4; ++r) {
        const int gi = min(max(gi0 + r, 0), NN - 1);
        #pragma unroll
        for (int c = 0; c < 4; ++c) {
            const int gj = min(max(gj0 + c, 0), NN - 1);
            v[r][c] = src[gi * NN + gj];
        }
    }

    // fixup / ownership flags (all intra-thread)
    const bool ifc      = (gj0 + 3 == 255);                 // interface col (bx==5, tx==5, c==3)
    const bool fix_rt   = (blockIdx.y == 0  && ty == 2);    // global row 0   <- row 1   (r0<-r1)
    const bool fix_rb   = (ro0 == 480       && ty == 9);    // global row 511 <- row 510 (r3<-r2)
    const bool fix_cl   = (blockIdx.x == 0  && tx == 2);    // global col 0   <- col 1   (c0<-c1)
    const bool fix_cr   = (co0 == 480       && tx == 9);    // global col 511 <- col 510 (c3<-c2)
    const bool store_ok = (tx >= 2 && tx < 14 && ty >= 2 && ty < 14 &&
                           gi0 < NN && gj0 < NN);

    float* __restrict__ slab = out + (size_t)t0 * N2;
    const unsigned FULL = 0xffffffffu;
    int pb = 0;

    for (int k = 0; k < nsteps; ++k) {
        // ---- vertical boundary exchange (old values) ----
        *(float4*)&s_top[pb][ty + 1][4 * tx] = make_float4(v[0][0], v[0][1], v[0][2], v[0][3]);
        *(float4*)&s_bot[pb][ty + 1][4 * tx] = make_float4(v[3][0], v[3][1], v[3][2], v[3][3]);
        __syncthreads();
        const float4 upv = *(const float4*)&s_bot[pb][ty][4 * tx];
        const float4 dnv = *(const float4*)&s_top[pb][ty + 2][4 * tx];
        const float up[4] = {upv.x, upv.y, upv.z, upv.w};
        const float dn[4] = {dnv.x, dnv.y, dnv.z, dnv.w};

        // ---- horizontal strip edges (old values; lane-crossing garbage stays in rim) ----
        float lft[4], rgt[4];
        #pragma unroll
        for (int r = 0; r < 4; ++r) {
            lft[r] = __shfl_up_sync(FULL,   v[r][3], 1);
            rgt[r] = __shfl_down_sync(FULL, v[r][0], 1);
        }

        // ---- 16 cell updates ----
        float n[4][4];
        #pragma unroll
        for (int r = 0; r < 4; ++r) {
            #pragma unroll
            for (int c = 0; c < 4; ++c) {
                const float cu = v[r][c];
                const float u_ = (r == 0) ? up[c] : v[r - 1][c];
                const float d_ = (r == 3) ? dn[c] : v[r + 1][c];
                const float l_ = (c == 0) ? lft[r] : v[r][c - 1];
                const float r_ = (c == 3) ? rgt[r] : v[r][c + 1];

                const float sum  = (u_ + d_) + (l_ + r_);
                const float lap  = fmaf(-4.0f, cu, sum);
                const float A    = fmaf(cu, d_ - u_, l_ - r_);
                const float adv  = cu * A;
                const float q    = fmaf(cu, cu, -cu);
                const float reac = cu * (q + 1.0f);

                float val = fmaf(c_al, lap, cu);
                val = fmaf(-cx, adv, val);
                val = fmaf(ck, reac, val);
                n[r][c] = val;
            }
        }

        // ---- interface column j=255: value from OLD neighbors (254, 256) ----
        if (ifc) {
            #pragma unroll
            for (int r = 0; r < 4; ++r)
                n[r][3] = (k1 * rgt[r] + k2 * v[r][2]) * inv_ksum;
        }

        // ---- domain-edge fixups (rows first, then cols — matches reference order) ----
        if (fix_rt) { n[0][0] = n[1][0]; n[0][1] = n[1][1]; n[0][2] = n[1][2]; n[0][3] = n[1][3]; }
        if (fix_rb) { n[3][0] = n[2][0]; n[3][1] = n[2][1]; n[3][2] = n[2][2]; n[3][3] = n[2][3]; }
        if (fix_cl) { n[0][0] = n[0][1]; n[1][0] = n[1][1]; n[2][0] = n[2][1]; n[3][0] = n[3][1]; }
        if (fix_cr) { n[0][3] = n[0][2]; n[1][3] = n[1][2]; n[2][3] = n[2][2]; n[3][3] = n[3][2]; }

        // ---- store owned 4x4 pack (coalesced 16B stores) ----
        if (store_ok) {
            #pragma unroll
            for (int r = 0; r < 4; ++r)
                *(float4*)&slab[(size_t)(gi0 + r) * NN + gj0] =
                    make_float4(n[r][0], n[r][1], n[r][2], n[r][3]);
        }

        slab += N2;
        #pragma unroll
        for (int r = 0; r < 4; ++r)
            #pragma unroll
            for (int c = 0; c < 4; ++c)
                v[r][c] = n[r][c];
        pb ^= 1;
    }
}

extern "C" void kernel_launch(void* const* d_in, const int* in_sizes, int n_in,
                              void* d_out, int out_size)
{
    const float* u0  = (const float*)d_in[0];
    const float* k1p = (const float*)d_in[1];
    const float* k2p = (const float*)d_in[2];
    const float* a1p = (const float*)d_in[3];
    const float* a2p = (const float*)d_in[4];
    float* out = (float*)d_out;

    dim3 block(16, 16, 1);
    dim3 grid((NN + TILEW - 1) / TILEW, (NN + TILEW - 1) / TILEW, 1);  // 11 x 11

    int t0 = 0;
    while (t0 < NSTEPS) {
        const int nsteps = min(S, NSTEPS - t0);
        const float* src = (t0 == 0) ? u0 : (out + (size_t)(t0 - 1) * N2);
        adr_chunk_kernel<<<grid, block>>>(src, out, t0, nsteps, k1p, k2p, a1p, a2p);
        t0 += nsteps;
    }
}